// round 14
// baseline (speedup 1.0000x reference)
#include <cuda_runtime.h>
#include <cuda_fp16.h>
#include <cstdint>

// ===========================================================================
// Kagome conv as implicit GEMM, fp16 single-pass mma.sync (fp32 accum).
// R14: M-split -> 2 CTAs per image (8 output rows x 128 co each), 512 thr,
// warp tile 32px x 32co (C=32 regs), __launch_bounds__(512,2) -> occ 2
// (32 warps/SM from independent CTAs). Per-image A/B L1 bytes CONSERVED
// vs R11 (A redundancy 4 via warpN, B redundancy 4 via warpM); only the
// 2-row staging halo duplicates (~11% of staging). ldmatrix A path,
// B register double-buffer, epilogue identical to R11.
// ===========================================================================

__constant__ int FDR[37] = {1,1,2,3,4,4,6,7,8,10,11,12,14,14,15,16,17,17,16,15,14,14,12,10,8,6,4,4,3,2,5,9,13,15,17,15,13};
__constant__ int FDC[37] = {3,5,7,9,10,11,13,13,14,15,15,16,15,16,15,14,13,11,9,7,6,5,3,2,1,0,0,1,1,2,0,2,4,8,12,14,16};
__constant__ int FSR[37] = {13,13,14,15,16,16,6,7,8,10,11,12,2,2,3,4,5,5,4,3,2,2,12,10,8,6,16,16,15,14,5,9,1,3,5,3,1};
__constant__ int FSC[37] = {15,5,7,9,10,11,1,1,2,3,3,4,3,4,3,2,1,11,9,7,6,5,15,14,13,12,12,13,13,14,12,14,4,8,12,2,4};

__constant__ unsigned MASKROW[16] = {
    0x0008u, 0x003Cu, 0x00FEu, 0x01FEu,
    0x0FFFu, 0x0FFFu, 0x0FFFu, 0x1FFEu,
    0x3FFCu, 0x3FFCu, 0x3FFCu, 0x7FF8u,
    0x7FF0u, 0x3FC0u, 0x1F00u, 0x1E00u
};

// W packed (same as R8/R11): index = ((((tap*8+g)*4+wn)*8+lr)*8+kq)*4+ns
// u32 = half2(ci, ci+1), co = wn*32+ns*8+lr, ci = g*16+2*kq.
__device__ unsigned int Wf[9 * 8 * 4 * 8 * 8 * 4];   // 73728 u32

#define PST 68                        // u32 per pos row; 68%32==4
#define NPOS 180                      // 10 padded rows x 18 cols per half
#define SMEM_BYTES (NPOS * PST * 4)   // 48,960 B

static __device__ __forceinline__ uint32_t packh2(float a, float b) {
    __half2 h = __floats2half2_rn(a, b);
    return *reinterpret_cast<uint32_t*>(&h);
}

static __device__ __forceinline__ void mma_fp16(float* c, const uint32_t* a,
                                                uint32_t b0, uint32_t b1) {
    asm volatile(
        "mma.sync.aligned.m16n8k16.row.col.f32.f16.f16.f32 "
        "{%0,%1,%2,%3}, {%4,%5,%6,%7}, {%8,%9}, {%0,%1,%2,%3};"
        : "+f"(c[0]), "+f"(c[1]), "+f"(c[2]), "+f"(c[3])
        : "r"(a[0]), "r"(a[1]), "r"(a[2]), "r"(a[3]), "r"(b0), "r"(b1));
}

static __device__ __forceinline__ void ldsm_x4(uint32_t* A, uint32_t addr) {
    asm volatile(
        "ldmatrix.sync.aligned.m8n8.x4.shared.b16 {%0,%1,%2,%3}, [%4];"
        : "=r"(A[0]), "=r"(A[1]), "=r"(A[2]), "=r"(A[3]) : "r"(addr));
}

// ---------------- prep: W -> Wf (unchanged) ----------------
__global__ void prep_w_kernel(const float* __restrict__ W) {
    int idx = blockIdx.x * 256 + threadIdx.x;
    if (idx >= 73728) return;
    int ns  = idx & 3;
    int kq  = (idx >> 2) & 7;
    int lr  = (idx >> 5) & 7;
    int wn  = (idx >> 8) & 3;
    int g   = (idx >> 10) & 7;
    int tap = idx >> 13;
    int co  = wn * 32 + ns * 8 + lr;
    int ci  = g * 16 + kq * 2;
    Wf[idx] = packh2(W[co * 1152 + ci * 9 + tap],
                     W[co * 1152 + (ci + 1) * 9 + tap]);
}

// ---------------- main ----------------
__global__ void __launch_bounds__(512, 2)
kagome_mma_kernel(const float* __restrict__ x,
                  const float* __restrict__ b,
                  float* __restrict__ out) {
    extern __shared__ uint32_t xpm[];   // [NPOS local pos][PST u32]

    const int tid   = threadIdx.x;
    const int wid   = tid >> 5;
    const int lane  = tid & 31;
    const int q     = lane & 3;
    const int lr    = lane >> 2;
    const int warpM = wid & 3;          // 4 groups of 2 m16-subtiles (32 px)
    const int warpN = wid >> 2;         // 4 groups of 32 co
    const int h     = blockIdx.x;       // image half: output rows h*8..h*8+7
    const int img   = blockIdx.y;

    const float* xg = x + (size_t)img * 128 * 256;
    const int rbase = 7 * h;            // staged input rows rbase..rbase+8

    // ---- zero whole local tile (pad cells must be 0) ----
    {
        uint4* z = (uint4*)xpm;
        #pragma unroll
        for (int i = 0; i < 6; i++) {
            int j = tid + i * 512;
            if (j < NPOS * PST / 4) z[j] = make_uint4(0, 0, 0, 0);
        }
    }
    __syncthreads();
    // ---- interior: 9 input rows x 16 px x 64 ci-pairs ----
    for (int j = tid; j < 64 * 36; j += 512) {    // 36 quads per pair
        int p    = j / 36;
        int quad = j - p * 36;
        int row_i = quad >> 2;                    // 0..8
        int colq  = (quad & 3) << 2;              // 0,4,8,12
        int r_in  = rbase + row_i;                // input row
        const float* s0 = xg + (2 * p) * 256 + r_in * 16 + colq;
        const float* s1 = s0 + 256;
        float4 r0 = *(const float4*)s0;
        float4 r1 = *(const float4*)s1;
        int lrow = r_in + 1 - 8 * h;              // local padded row 1..9 / 0..9
        uint32_t* d = xpm + (lrow * 18 + colq + 1) * PST + p;
        d[0]       = packh2(r0.x, r1.x);
        d[PST]     = packh2(r0.y, r1.y);
        d[2 * PST] = packh2(r0.z, r1.z);
        d[3 * PST] = packh2(r0.w, r1.w);
    }
    __syncthreads();   // interior visible before fixups overwrite
    // ---- boundary fixups landing in this half's padded rows ----
    for (int j = tid; j < 64 * 37; j += 512) {
        int p = j / 37, f = j - p * 37;
        int dr = FDR[f];
        if (dr >= 8 * h && dr < 8 * h + 10) {
            int spx = (FSR[f] - 1) * 16 + (FSC[f] - 1);
            xpm[((dr - 8 * h) * 18 + FDC[f]) * PST + p] =
                packh2(xg[(2 * p) * 256 + spx], xg[(2 * p + 1) * 256 + spx]);
        }
    }
    __syncthreads();

    // ---- mainloop: 72 iterations (9 taps x 8 ci-groups) ----
    float C[2][4][4];
    #pragma unroll
    for (int s = 0; s < 2; s++)
        #pragma unroll
        for (int n = 0; n < 4; n++)
            #pragma unroll
            for (int e = 0; e < 4; e++) C[s][n][e] = 0.f;

    const uint32_t sb = (uint32_t)__cvta_generic_to_shared(xpm);
    const uint32_t laneoff = (((lane & 15) * PST) + (lane >> 4) * 4) * 4;

    const uint32_t* wbase = Wf + ((warpN * 8) + lr) * 32 + q * 4;
    uint4 Bs[2][2];
    Bs[0][0] = __ldg((const uint4*)(wbase));
    Bs[0][1] = __ldg((const uint4*)(wbase + 16));
    Bs[1][0] = __ldg((const uint4*)(wbase + 1024));
    Bs[1][1] = __ldg((const uint4*)(wbase + 1024 + 16));

    #pragma unroll 2
    for (int u = 0; u < 72; u++) {
        const int tap = u >> 3, g = u & 7;
        const int kr = (tap >= 6) ? 2 : (tap >= 3 ? 1 : 0);
        const int toff = kr * 18 + (tap - kr * 3);   // kr*18 + kc

        uint4 b0 = Bs[u & 1][0];
        uint4 b1 = Bs[u & 1][1];
        if (u < 70) {
            const uint32_t* wp = wbase + (u + 2) * 1024;
            Bs[u & 1][0] = __ldg((const uint4*)(wp));
            Bs[u & 1][1] = __ldg((const uint4*)(wp + 16));
        }

        #pragma unroll
        for (int s = 0; s < 2; s++) {
            int Rl = warpM * 2 + s;                  // local output row 0..7
            uint32_t addr = sb + (uint32_t)(((Rl * 18 + toff) * PST + g * 8) * 4)
                          + laneoff;
            uint32_t A[4];
            ldsm_x4(A, addr);
            mma_fp16(C[s][0], A, b0.x, b1.x);
            mma_fp16(C[s][1], A, b0.y, b1.y);
            mma_fp16(C[s][2], A, b0.z, b1.z);
            mma_fp16(C[s][3], A, b0.w, b1.w);
        }
    }

    // ---- epilogue: +bias, *mask, store ----
    float* og = out + (size_t)img * 128 * 256;
    #pragma unroll
    for (int ns = 0; ns < 4; ns++) {
        int co0 = warpN * 32 + ns * 8 + 2 * q;
        float bv0 = __ldg(b + co0);
        float bv1 = __ldg(b + co0 + 1);
        #pragma unroll
        for (int s = 0; s < 2; s++) {
            int R = h * 8 + warpM * 2 + s;           // global output row
            unsigned mrow = MASKROW[R];
            float k0 = ((mrow >> lr) & 1u) ? 1.f : 0.f;
            float k1 = ((mrow >> (lr + 8)) & 1u) ? 1.f : 0.f;
            int p0 = R * 16 + lr;
            int p1 = p0 + 8;
            og[co0 * 256 + p0]       = (C[s][ns][0] + bv0) * k0;
            og[(co0 + 1) * 256 + p0] = (C[s][ns][1] + bv1) * k0;
            og[co0 * 256 + p1]       = (C[s][ns][2] + bv0) * k1;
            og[(co0 + 1) * 256 + p1] = (C[s][ns][3] + bv1) * k1;
        }
    }
}

extern "C" void kernel_launch(void* const* d_in, const int* in_sizes, int n_in,
                              void* d_out, int out_size) {
    (void)in_sizes; (void)n_in; (void)out_size;
    const float* x = (const float*)d_in[0];
    const float* W = (const float*)d_in[1];
    const float* b = (const float*)d_in[2];
    float* out = (float*)d_out;

    cudaFuncSetAttribute(kagome_mma_kernel,
                         cudaFuncAttributeMaxDynamicSharedMemorySize, SMEM_BYTES);

    prep_w_kernel<<<288, 256>>>(W);
    dim3 grid(2, 2048);
    kagome_mma_kernel<<<grid, 512, SMEM_BYTES>>>(x, b, out);
}

// round 15
// speedup vs baseline: 2.0257x; 2.0257x over previous
#include <cuda_runtime.h>
#include <cuda_fp16.h>
#include <cstdint>

// ===========================================================================
// Kagome conv as implicit GEMM, fp16 single-pass mma.sync (fp32 accum).
// R15: occupancy 2 with the warp tile UNCHANGED (the R10/R12/R14 failures
// all shrank the warp tile; R11's 64px x 32co is geometry-optimal).
// CTA = 256 threads / 8 warps = 2 warpM x 4 warpN = 128px x 128co;
// 2 CTAs per image (M-split). C = 64 regs/thread, 256thr x 128regs = 32K
// -> exactly 2 CTAs/SM. Per-SM warp count, warp-iter cost, and A/B
// redundancy all identical to R11; the win is cross-CTA overlap of
// staging/epilogue with mainloop. ldmatrix A path + B double-buffer = R11.
// ===========================================================================

__constant__ int FDR[37] = {1,1,2,3,4,4,6,7,8,10,11,12,14,14,15,16,17,17,16,15,14,14,12,10,8,6,4,4,3,2,5,9,13,15,17,15,13};
__constant__ int FDC[37] = {3,5,7,9,10,11,13,13,14,15,15,16,15,16,15,14,13,11,9,7,6,5,3,2,1,0,0,1,1,2,0,2,4,8,12,14,16};
__constant__ int FSR[37] = {13,13,14,15,16,16,6,7,8,10,11,12,2,2,3,4,5,5,4,3,2,2,12,10,8,6,16,16,15,14,5,9,1,3,5,3,1};
__constant__ int FSC[37] = {15,5,7,9,10,11,1,1,2,3,3,4,3,4,3,2,1,11,9,7,6,5,15,14,13,12,12,13,13,14,12,14,4,8,12,2,4};

__constant__ unsigned MASKROW[16] = {
    0x0008u, 0x003Cu, 0x00FEu, 0x01FEu,
    0x0FFFu, 0x0FFFu, 0x0FFFu, 0x1FFEu,
    0x3FFCu, 0x3FFCu, 0x3FFCu, 0x7FF8u,
    0x7FF0u, 0x3FC0u, 0x1F00u, 0x1E00u
};

// W packed (same as R8/R11): index = ((((tap*8+g)*4+wn)*8+lr)*8+kq)*4+ns
// u32 = half2(ci, ci+1), co = wn*32+ns*8+lr, ci = g*16+2*kq.
__device__ unsigned int Wf[9 * 8 * 4 * 8 * 8 * 4];   // 73728 u32

#define PST 68                        // u32 per pos row; 68%32==4
#define NPOS 180                      // 10 padded rows x 18 cols per half
#define SMEM_BYTES (NPOS * PST * 4)   // 48,960 B

static __device__ __forceinline__ uint32_t packh2(float a, float b) {
    __half2 h = __floats2half2_rn(a, b);
    return *reinterpret_cast<uint32_t*>(&h);
}

static __device__ __forceinline__ void mma_fp16(float* c, const uint32_t* a,
                                                uint32_t b0, uint32_t b1) {
    asm volatile(
        "mma.sync.aligned.m16n8k16.row.col.f32.f16.f16.f32 "
        "{%0,%1,%2,%3}, {%4,%5,%6,%7}, {%8,%9}, {%0,%1,%2,%3};"
        : "+f"(c[0]), "+f"(c[1]), "+f"(c[2]), "+f"(c[3])
        : "r"(a[0]), "r"(a[1]), "r"(a[2]), "r"(a[3]), "r"(b0), "r"(b1));
}

static __device__ __forceinline__ void ldsm_x4(uint32_t* A, uint32_t addr) {
    asm volatile(
        "ldmatrix.sync.aligned.m8n8.x4.shared.b16 {%0,%1,%2,%3}, [%4];"
        : "=r"(A[0]), "=r"(A[1]), "=r"(A[2]), "=r"(A[3]) : "r"(addr));
}

// ---------------- prep: W -> Wf (unchanged) ----------------
__global__ void prep_w_kernel(const float* __restrict__ W) {
    int idx = blockIdx.x * 256 + threadIdx.x;
    if (idx >= 73728) return;
    int ns  = idx & 3;
    int kq  = (idx >> 2) & 7;
    int lr  = (idx >> 5) & 7;
    int wn  = (idx >> 8) & 3;
    int g   = (idx >> 10) & 7;
    int tap = idx >> 13;
    int co  = wn * 32 + ns * 8 + lr;
    int ci  = g * 16 + kq * 2;
    Wf[idx] = packh2(W[co * 1152 + ci * 9 + tap],
                     W[co * 1152 + (ci + 1) * 9 + tap]);
}

// ---------------- main ----------------
__global__ void __launch_bounds__(256, 2)
kagome_mma_kernel(const float* __restrict__ x,
                  const float* __restrict__ b,
                  float* __restrict__ out) {
    extern __shared__ uint32_t xpm[];   // [NPOS local pos][PST u32]

    const int tid   = threadIdx.x;
    const int wid   = tid >> 5;
    const int lane  = tid & 31;
    const int q     = lane & 3;
    const int lr    = lane >> 2;
    const int warpM = wid & 1;          // 2 groups of 4 m16-subtiles (64 px)
    const int warpN = wid >> 1;         // 4 groups of 32 co
    const int h     = blockIdx.x;       // image half: output rows h*8..h*8+7
    const int img   = blockIdx.y;

    const float* xg = x + (size_t)img * 128 * 256;
    const int rbase = 7 * h;            // staged input rows rbase..rbase+8

    // ---- zero whole local tile (pad cells must be 0) ----
    {
        uint4* z = (uint4*)xpm;
        #pragma unroll
        for (int i = 0; i < 12; i++) {
            int j = tid + i * 256;
            if (j < NPOS * PST / 4) z[j] = make_uint4(0, 0, 0, 0);
        }
    }
    __syncthreads();
    // ---- interior: 9 input rows x 16 px x 64 ci-pairs ----
    for (int j = tid; j < 64 * 36; j += 256) {    // 36 quads per pair
        int p    = j / 36;
        int quad = j - p * 36;
        int row_i = quad >> 2;                    // 0..8
        int colq  = (quad & 3) << 2;              // 0,4,8,12
        int r_in  = rbase + row_i;                // input row
        const float* s0 = xg + (2 * p) * 256 + r_in * 16 + colq;
        const float* s1 = s0 + 256;
        float4 r0 = *(const float4*)s0;
        float4 r1 = *(const float4*)s1;
        int lrow = r_in + 1 - 8 * h;              // local padded row 0..9
        uint32_t* d = xpm + (lrow * 18 + colq + 1) * PST + p;
        d[0]       = packh2(r0.x, r1.x);
        d[PST]     = packh2(r0.y, r1.y);
        d[2 * PST] = packh2(r0.z, r1.z);
        d[3 * PST] = packh2(r0.w, r1.w);
    }
    __syncthreads();   // interior visible before fixups overwrite
    // ---- boundary fixups landing in this half's padded rows ----
    for (int j = tid; j < 64 * 37; j += 256) {
        int p = j / 37, f = j - p * 37;
        int dr = FDR[f];
        if (dr >= 8 * h && dr < 8 * h + 10) {
            int spx = (FSR[f] - 1) * 16 + (FSC[f] - 1);
            xpm[((dr - 8 * h) * 18 + FDC[f]) * PST + p] =
                packh2(xg[(2 * p) * 256 + spx], xg[(2 * p + 1) * 256 + spx]);
        }
    }
    __syncthreads();

    // ---- mainloop: 72 iterations (9 taps x 8 ci-groups) ----
    float C[4][4][4];
    #pragma unroll
    for (int s = 0; s < 4; s++)
        #pragma unroll
        for (int n = 0; n < 4; n++)
            #pragma unroll
            for (int e = 0; e < 4; e++) C[s][n][e] = 0.f;

    const uint32_t sb = (uint32_t)__cvta_generic_to_shared(xpm);
    const uint32_t laneoff = (((lane & 15) * PST) + (lane >> 4) * 4) * 4;

    const uint32_t* wbase = Wf + ((warpN * 8) + lr) * 32 + q * 4;
    uint4 Bs[2][2];
    Bs[0][0] = __ldg((const uint4*)(wbase));
    Bs[0][1] = __ldg((const uint4*)(wbase + 16));
    Bs[1][0] = __ldg((const uint4*)(wbase + 1024));
    Bs[1][1] = __ldg((const uint4*)(wbase + 1024 + 16));

    #pragma unroll 2
    for (int u = 0; u < 72; u++) {
        const int tap = u >> 3, g = u & 7;
        const int kr = (tap >= 6) ? 2 : (tap >= 3 ? 1 : 0);
        const int toff = kr * 18 + (tap - kr * 3);   // kr*18 + kc

        uint4 b0 = Bs[u & 1][0];
        uint4 b1 = Bs[u & 1][1];
        if (u < 70) {
            const uint32_t* wp = wbase + (u + 2) * 1024;
            Bs[u & 1][0] = __ldg((const uint4*)(wp));
            Bs[u & 1][1] = __ldg((const uint4*)(wp + 16));
        }

        #pragma unroll
        for (int s = 0; s < 4; s++) {
            int Rl = warpM * 4 + s;                  // local output row 0..7
            uint32_t addr = sb + (uint32_t)(((Rl * 18 + toff) * PST + g * 8) * 4)
                          + laneoff;
            uint32_t A[4];
            ldsm_x4(A, addr);
            mma_fp16(C[s][0], A, b0.x, b1.x);
            mma_fp16(C[s][1], A, b0.y, b1.y);
            mma_fp16(C[s][2], A, b0.z, b1.z);
            mma_fp16(C[s][3], A, b0.w, b1.w);
        }
    }

    // ---- epilogue: +bias, *mask, store ----
    float* og = out + (size_t)img * 128 * 256;
    #pragma unroll
    for (int ns = 0; ns < 4; ns++) {
        int co0 = warpN * 32 + ns * 8 + 2 * q;
        float bv0 = __ldg(b + co0);
        float bv1 = __ldg(b + co0 + 1);
        #pragma unroll
        for (int s = 0; s < 4; s++) {
            int R = h * 8 + warpM * 4 + s;           // global output row
            unsigned mrow = MASKROW[R];
            float k0 = ((mrow >> lr) & 1u) ? 1.f : 0.f;
            float k1 = ((mrow >> (lr + 8)) & 1u) ? 1.f : 0.f;
            int p0 = R * 16 + lr;
            int p1 = p0 + 8;
            og[co0 * 256 + p0]       = (C[s][ns][0] + bv0) * k0;
            og[(co0 + 1) * 256 + p0] = (C[s][ns][1] + bv1) * k0;
            og[co0 * 256 + p1]       = (C[s][ns][2] + bv0) * k1;
            og[(co0 + 1) * 256 + p1] = (C[s][ns][3] + bv1) * k1;
        }
    }
}

extern "C" void kernel_launch(void* const* d_in, const int* in_sizes, int n_in,
                              void* d_out, int out_size) {
    (void)in_sizes; (void)n_in; (void)out_size;
    const float* x = (const float*)d_in[0];
    const float* W = (const float*)d_in[1];
    const float* b = (const float*)d_in[2];
    float* out = (float*)d_out;

    cudaFuncSetAttribute(kagome_mma_kernel,
                         cudaFuncAttributeMaxDynamicSharedMemorySize, SMEM_BYTES);

    prep_w_kernel<<<288, 256>>>(W);
    dim3 grid(2, 2048);
    kagome_mma_kernel<<<grid, 256, SMEM_BYTES>>>(x, b, out);
}